// round 3
// baseline (speedup 1.0000x reference)
#include <cuda_runtime.h>
#include <math.h>

#define BETA 0.1f
#define NTILES 8192
#define GRID   1216   // 152 SMs * 8 resident blocks -> single persistent wave

// Persistent-grid kernel: each block loops over tiles bp, bp+GRID, ...
// Input: x_cat[b, 2p+s, k]; tile bp's h-row at +bp*128, v-row at +bp*128+64.
// Output: places at out + bp*4096, sampled at out + half + bp*4096.
__global__ __launch_bounds__(256, 8)
void spatial_sampler_kernel(const float* __restrict__ x_cat,
                            const float* __restrict__ noise,
                            float* __restrict__ out,
                            long long half_elems)
{
    __shared__ float sx[128];   // [0:64) h row, [64:128) v row
    __shared__ float ss[128];   // masked (sampled) rows
    __shared__ float wmax[4];

    const int tid  = threadIdx.x;
    const bool act = (tid < 128);

    // prefetch first tile
    int bp = blockIdx.x;
    float xv = 0.f, nv = 0.f;
    if (act && bp < NTILES) {
        xv = x_cat[(long long)bp * 128 + tid];
        nv = noise[(long long)bp * 128 + tid];
    }

    for (; bp < NTILES; bp += GRID) {
        // --- log_pdf + per-row max (each 64-wide row = 2 warps) ---
        float lp = -INFINITY;
        if (act) {
            lp = logf(xv) + BETA * nv;
            sx[tid] = xv;
        }
        float m = lp;
        #pragma unroll
        for (int off = 16; off > 0; off >>= 1)
            m = fmaxf(m, __shfl_xor_sync(0xffffffffu, m, off));
        if (act && (tid & 31) == 0)
            wmax[tid >> 5] = m;
        __syncthreads();

        if (act) {
            float rowmax = (tid < 64) ? fmaxf(wmax[0], wmax[1])
                                      : fmaxf(wmax[2], wmax[3]);
            ss[tid] = (lp == rowmax) ? xv : 0.f;
        }
        __syncthreads();

        // --- prefetch next tile while stores stream out ---
        const int bpn = bp + GRID;
        float nxv = 0.f, nnv = 0.f;
        if (act && bpn < NTILES) {
            nxv = x_cat[(long long)bpn * 128 + tid];
            nnv = noise[(long long)bpn * 128 + tid];
        }

        // --- write both 64x64 tiles, float4, coalesced ---
        float4* p4 = reinterpret_cast<float4*>(out + (long long)bp * 4096);
        float4* s4 = reinterpret_cast<float4*>(out + half_elems + (long long)bp * 4096);
        const float4* v4  = reinterpret_cast<const float4*>(&sx[64]);
        const float4* sv4 = reinterpret_cast<const float4*>(&ss[64]);

        #pragma unroll
        for (int it = 0; it < 4; ++it) {
            const int i  = tid + it * 256;
            const int j  = i >> 4;        // row 0..63
            const int c4 = i & 15;        // float4 col 0..15

            const float hj = sx[j];
            float4 vv = v4[c4];
            float4 o;
            o.x = hj * vv.x; o.y = hj * vv.y; o.z = hj * vv.z; o.w = hj * vv.w;
            p4[i] = o;

            const float shj = ss[j] * 100.0f;
            float4 sv = sv4[c4];
            float4 so;
            so.x = shj * sv.x; so.y = shj * sv.y; so.z = shj * sv.z; so.w = shj * sv.w;
            s4[i] = so;
        }

        xv = nxv; nv = nnv;
        __syncthreads();   // sx/ss reuse next iteration
    }
}

extern "C" void kernel_launch(void* const* d_in, const int* in_sizes, int n_in,
                              void* d_out, int out_size)
{
    const float* x_cat = (const float*)d_in[0];
    const float* noise = (const float*)d_in[1];
    float* out = (float*)d_out;

    const long long half = (long long)out_size / 2;

    spatial_sampler_kernel<<<GRID, 256>>>(x_cat, noise, out, half);
}

// round 4
// speedup vs baseline: 1.0766x; 1.0766x over previous
#include <cuda_runtime.h>
#include <math.h>

#define BETA 0.1f
#define FULL 0xffffffffu

// Warp-autonomous: ONE WARP per (b,p) tile. No shared memory, no block barriers.
// Each lane holds 4 x-values: h[lid], h[32+lid], v[lid], v[32+lid].
// Row-max via shfl_xor; outer-product stores via shfl broadcasts.
// 8 warps per 256-thread block -> grid = 8192/8 = 1024 blocks.
__global__ __launch_bounds__(256, 8)
void spatial_sampler_kernel(const float* __restrict__ x_cat,
                            const float* __restrict__ noise,
                            float* __restrict__ out,
                            long long half_elems)
{
    const int lid = threadIdx.x & 31;
    const int bp  = blockIdx.x * 8 + (threadIdx.x >> 5);   // tile id 0..8191

    const long long base = (long long)bp * 128;
    // h row = x[base..base+63], v row = x[base+64..base+127]
    const float x0 = __ldg(&x_cat[base + lid]);        // h[lid]
    const float x1 = __ldg(&x_cat[base + 32 + lid]);   // h[32+lid]
    const float x2 = __ldg(&x_cat[base + 64 + lid]);   // v[lid]
    const float x3 = __ldg(&x_cat[base + 96 + lid]);   // v[32+lid]
    const float n0 = __ldg(&noise[base + lid]);
    const float n1 = __ldg(&noise[base + 32 + lid]);
    const float n2 = __ldg(&noise[base + 64 + lid]);
    const float n3 = __ldg(&noise[base + 96 + lid]);

    const float lp0 = logf(x0) + BETA * n0;
    const float lp1 = logf(x1) + BETA * n1;
    const float lp2 = logf(x2) + BETA * n2;
    const float lp3 = logf(x3) + BETA * n3;

    // row maxima across the warp
    float mh = fmaxf(lp0, lp1);
    float mv = fmaxf(lp2, lp3);
    #pragma unroll
    for (int off = 16; off > 0; off >>= 1) {
        mh = fmaxf(mh, __shfl_xor_sync(FULL, mh, off));
        mv = fmaxf(mv, __shfl_xor_sync(FULL, mv, off));
    }

    // masked rows (sampled); fold the *100 into the h side
    const float sh0 = (lp0 == mh) ? x0 * 100.0f : 0.f;
    const float sh1 = (lp1 == mh) ? x1 * 100.0f : 0.f;
    const float sv2 = (lp2 == mv) ? x2 : 0.f;
    const float sv3 = (lp3 == mv) ? x3 : 0.f;

    // Per-lane column group: cc = lid & 15 -> columns 4cc..4cc+3.
    // Gather the 4 v-values (and masked v-values) for those columns once.
    const int cc = lid & 15;
    float4 vv, sv;
    {
        const int i0 = 4 * cc;
        #pragma unroll
        for (int q = 0; q < 4; ++q) {
            const int idx = i0 + q;
            const float lo  = __shfl_sync(FULL, x2,  idx & 31);
            const float hi  = __shfl_sync(FULL, x3,  idx & 31);
            const float slo = __shfl_sync(FULL, sv2, idx & 31);
            const float shi = __shfl_sync(FULL, sv3, idx & 31);
            const float v  = (idx < 32) ? lo  : hi;
            const float s  = (idx < 32) ? slo : shi;
            if (q == 0) { vv.x = v; sv.x = s; }
            else if (q == 1) { vv.y = v; sv.y = s; }
            else if (q == 2) { vv.z = v; sv.z = s; }
            else { vv.w = v; sv.w = s; }
        }
    }

    // Store both 64x64 tiles. Per iteration the warp writes 2 adjacent rows
    // (512 contiguous bytes) of each output: lanes 0-15 row r, 16-31 row r+1.
    float4* p4 = reinterpret_cast<float4*>(out + (long long)bp * 4096);
    float4* s4 = reinterpret_cast<float4*>(out + half_elems + (long long)bp * 4096);
    const int rbit = lid >> 4;   // which of the two rows this lane covers

    #pragma unroll 8
    for (int it = 0; it < 32; ++it) {
        const int r = 2 * it + rbit;                 // row 0..63
        const float hsrc  = (it < 16) ? x0  : x1;    // h[r] lives in x0 or x1
        const float shsrc = (it < 16) ? sh0 : sh1;
        const float hr  = __shfl_sync(FULL, hsrc,  r & 31);
        const float shr = __shfl_sync(FULL, shsrc, r & 31);

        float4 o;
        o.x = hr * vv.x; o.y = hr * vv.y; o.z = hr * vv.z; o.w = hr * vv.w;
        p4[r * 16 + cc] = o;

        float4 so;
        so.x = shr * sv.x; so.y = shr * sv.y; so.z = shr * sv.z; so.w = shr * sv.w;
        s4[r * 16 + cc] = so;
    }
}

extern "C" void kernel_launch(void* const* d_in, const int* in_sizes, int n_in,
                              void* d_out, int out_size)
{
    const float* x_cat = (const float*)d_in[0];
    const float* noise = (const float*)d_in[1];
    float* out = (float*)d_out;

    const long long half = (long long)out_size / 2;
    const int tiles = in_sizes[0] / 128;     // 8192
    spatial_sampler_kernel<<<tiles / 8, 256>>>(x_cat, noise, out, half);
}

// round 5
// speedup vs baseline: 1.1293x; 1.0489x over previous
#include <cuda_runtime.h>
#include <math.h>

#define BETA 0.1f

// One block per (b,p) tile, 256 threads.
// Store phase is de-interleaved: warps 0-3 (tid 0..127) write the whole
// `places` tile; warps 4-7 (tid 128..255) write the whole `sampled` tile.
// Each half-block covers 1024 float4 in 8 coalesced iterations.
__global__ __launch_bounds__(256, 8)
void spatial_sampler_kernel(const float* __restrict__ x_cat,
                            const float* __restrict__ noise,
                            float* __restrict__ out,
                            long long half_elems)
{
    __shared__ float sx[128];   // [0:64) h row, [64:128) v row
    __shared__ float ss[128];   // masked rows (h part pre-scaled by 100)
    __shared__ float wmax[4];

    const int bp  = blockIdx.x;
    const int tid = threadIdx.x;

    const float* xrow = x_cat + (long long)bp * 128;
    const float* nrow = noise + (long long)bp * 128;

    // --- load + log_pdf + per-row max (each 64-wide row = 2 warps) ---
    float lp = -INFINITY;
    float xv = 0.f;
    if (tid < 128) {
        xv = xrow[tid];
        lp = logf(xv) + BETA * nrow[tid];
        sx[tid] = xv;
    }
    float m = lp;
    #pragma unroll
    for (int off = 16; off > 0; off >>= 1)
        m = fmaxf(m, __shfl_xor_sync(0xffffffffu, m, off));
    if (tid < 128 && (tid & 31) == 0)
        wmax[tid >> 5] = m;
    __syncthreads();

    if (tid < 128) {
        float rowmax = (tid < 64) ? fmaxf(wmax[0], wmax[1])
                                  : fmaxf(wmax[2], wmax[3]);
        float s = (lp == rowmax) ? xv : 0.f;
        // fold *100 into the h half so the store loop is a plain product
        ss[tid] = (tid < 64) ? s * 100.0f : s;
    }
    __syncthreads();

    // --- de-interleaved stores: half-block per output tensor ---
    const int  half_tid = tid & 127;          // 0..127 within the half-block
    const bool is_samp  = (tid >= 128);

    const float* hsrc = is_samp ? ss       : sx;
    const float* vsrc = is_samp ? &ss[64]  : &sx[64];
    float4* dst = reinterpret_cast<float4*>(
        out + (is_samp ? half_elems : 0) + (long long)bp * 4096);

    const float4* v4 = reinterpret_cast<const float4*>(vsrc);

    #pragma unroll
    for (int it = 0; it < 8; ++it) {
        const int i  = half_tid + it * 128;   // 0..1023 float4 index
        const int j  = i >> 4;                // row 0..63
        const int c4 = i & 15;                // float4 col 0..15

        const float hj = hsrc[j];
        float4 vv = v4[c4];
        float4 o;
        o.x = hj * vv.x; o.y = hj * vv.y; o.z = hj * vv.z; o.w = hj * vv.w;
        dst[i] = o;
    }
}

extern "C" void kernel_launch(void* const* d_in, const int* in_sizes, int n_in,
                              void* d_out, int out_size)
{
    const float* x_cat = (const float*)d_in[0];
    const float* noise = (const float*)d_in[1];
    float* out = (float*)d_out;

    const long long half = (long long)out_size / 2;
    const int tiles = in_sizes[0] / 128;   // 8192 (b,p) tiles

    spatial_sampler_kernel<<<tiles, 256>>>(x_cat, noise, out, half);
}